// round 7
// baseline (speedup 1.0000x reference)
#include <cuda_runtime.h>
#include <cuda_bf16.h>
#include <stdint.h>

// GAE forward: A_hat = sigmoid(Z Z^T), Z = A @ (relu(A @ (X W1)) @ W2)
// N=8192, F_IN=256, HID=128, LAT=32.
// Round 6: k1 re-tiled to BM=32/grid 1024 (k3's winning occupancy recipe),
// k3 SPLIT2 16, k4 two-pass epilogue (half the acc regs -> 3 CTA/SM),
// k0 uses packed fma.rn.f32x2 (FFMA2) for 2x fp32 FMA throughput.

constexpr int NN  = 8192;
constexpr int FIN = 256;
constexpr int HID = 128;
constexpr int LAT = 32;

constexpr int SPLIT1 = 4;    // k1: grid (256, 4)  = 1024 CTAs
constexpr int SPLIT2 = 16;   // k3: grid (256, 16) = 4096 CTAs

__device__ __nv_bfloat16 g_C1t[HID * NN];          // (X W1)^T  [128][8192] bf16
__device__ __nv_bfloat16 g_C2t[LAT * NN];          // (H W2)^T  [32][8192]  bf16
__device__ __nv_bfloat16 g_Z  [NN * LAT];          // Z         [8192][32]  bf16
__device__ float g_P1[SPLIT1 * NN * HID];          // k1 partials (16 MB)
__device__ float g_P2[SPLIT2 * NN * LAT];          // k3 partials (16 MB)

__device__ __forceinline__ void mma_bf16(float c[4], const uint32_t a[4], const uint32_t b[2]) {
    asm volatile(
        "mma.sync.aligned.m16n8k16.row.col.f32.bf16.bf16.f32 "
        "{%0,%1,%2,%3}, {%4,%5,%6,%7}, {%8,%9}, {%0,%1,%2,%3};\n"
        : "+f"(c[0]), "+f"(c[1]), "+f"(c[2]), "+f"(c[3])
        : "r"(a[0]), "r"(a[1]), "r"(a[2]), "r"(a[3]), "r"(b[0]), "r"(b[1]));
}

__device__ __forceinline__ uint32_t pack_bf16x2(float x, float y) {
    __nv_bfloat162 v = __float22bfloat162_rn(make_float2(x, y));
    return *reinterpret_cast<uint32_t*>(&v);
}

// Packed fp32x2 FMA (Blackwell FFMA2; only reachable via PTX).
__device__ __forceinline__ void ffma2(unsigned long long& acc,
                                      unsigned long long a, unsigned long long b) {
    asm("fma.rn.f32x2 %0, %1, %2, %0;" : "+l"(acc) : "l"(a), "l"(b));
}
__device__ __forceinline__ unsigned long long pk2(float lo, float hi) {
    unsigned long long r;
    asm("mov.b64 %0, {%1, %2};" : "=l"(r) : "f"(lo), "f"(hi));
    return r;
}
__device__ __forceinline__ float2 upk2(unsigned long long v) {
    float2 r;
    asm("mov.b64 {%0, %1}, %2;" : "=f"(r.x), "=f"(r.y) : "l"(v));
    return r;
}

__device__ __forceinline__ float sigmoid_f(float x) {
    float ax = fabsf(x);
    if (ax < 1.0f) {
        float x2 = x * x;   // |err| < 2.2e-5 on |x|<1; real |x| ~ 1e-8 here
        return 0.5f + x * (0.25f + x2 * (-(1.0f / 48.0f) + x2 * (1.0f / 480.0f)));
    }
    return 1.0f / (1.0f + __expf(-x));
}

// ---------------------------------------------------------------------------
// k0: C1t = (X @ W1)^T as bf16. FFMA2 SIMT. BM=32, grid 256, block 256.
// ---------------------------------------------------------------------------
__global__ __launch_bounds__(256) void k0_xw1(const float* __restrict__ X,
                                              const float* __restrict__ W1) {
    __shared__ float Xs[32][32];
    __shared__ float Ws[32][128];
    const int tid = threadIdx.x;
    const int r0  = blockIdx.x * 32;
    const int ty  = tid >> 5, tx = tid & 31;

    unsigned long long acc2[4][2];
#pragma unroll
    for (int i = 0; i < 4; ++i) { acc2[i][0] = pk2(0.f, 0.f); acc2[i][1] = pk2(0.f, 0.f); }

    for (int kt = 0; kt < FIN; kt += 32) {
        {
            int rr = tid >> 3, cc = (tid & 7) * 4;
            *(float4*)&Xs[rr][cc] = *(const float4*)&X[(size_t)(r0 + rr) * FIN + kt + cc];
        }
#pragma unroll
        for (int j = 0; j < 4; ++j) {
            int id = tid + j * 256;
            int rr = id >> 5, cc = (id & 31) * 4;
            *(float4*)&Ws[rr][cc] = *(const float4*)&W1[(size_t)(kt + rr) * HID + cc];
        }
        __syncthreads();
#pragma unroll
        for (int k = 0; k < 32; ++k) {
            float4 b = *(float4*)&Ws[k][tx * 4];
            unsigned long long b01 = pk2(b.x, b.y), b23 = pk2(b.z, b.w);
#pragma unroll
            for (int i = 0; i < 4; ++i) {
                float a = Xs[ty * 4 + i][k];
                unsigned long long aa = pk2(a, a);
                ffma2(acc2[i][0], aa, b01);
                ffma2(acc2[i][1], aa, b23);
            }
        }
        __syncthreads();
    }
#pragma unroll
    for (int i = 0; i < 4; ++i) {
        float2 v01 = upk2(acc2[i][0]), v23 = upk2(acc2[i][1]);
        float v[4] = {v01.x, v01.y, v23.x, v23.y};
#pragma unroll
        for (int j = 0; j < 4; ++j)
            g_C1t[(size_t)(tx * 4 + j) * NN + r0 + ty * 4 + i] = __float2bfloat16(v[j]);
    }
}

// ---------------------------------------------------------------------------
// k1: split-K partial of A @ C1. BM=32, BN=128, BK=32.
// grid (256, SPLIT1) = 1024 CTAs, 256 thr, double-buffered smem.
// Warps 2m x 4n (16x32 warp tile). Writes fp32 partials.
// ---------------------------------------------------------------------------
__global__ __launch_bounds__(256) void k1_gemm1(const float* __restrict__ A) {
    __shared__ __nv_bfloat16 As[2][32][40];
    __shared__ __nv_bfloat16 Bs[2][128][40];

    const int tid  = threadIdx.x;
    const int warp = tid >> 5, lane = tid & 31;
    const int g = lane >> 2, t = lane & 3;
    const int mw = warp & 1, nw = warp >> 1;
    const int m0 = mw * 16, n0 = nw * 32;
    const int r0  = blockIdx.x * 32;
    const int sp  = blockIdx.y;
    const int ks0 = sp * (NN / SPLIT1);

    const int ar = tid >> 3, ac = (tid & 7) * 4;   // A: 32x32 fp32, 1 float4/thr
    const int br = tid >> 2, bc = (tid & 3) * 8;   // B: rows br, br+64

    float acc[4][4];
#pragma unroll
    for (int f = 0; f < 4; ++f)
#pragma unroll
        for (int j = 0; j < 4; ++j) acc[f][j] = 0.0f;

    float4 pa0;
    uint4  pb0, pb1;
    pa0 = __ldcs((const float4*)&A[(size_t)(r0 + ar) * NN + ks0 + ac]);
    pb0 = *(const uint4*)&g_C1t[(size_t)br * NN + ks0 + bc];
    pb1 = *(const uint4*)&g_C1t[(size_t)(br + 64) * NN + ks0 + bc];

    *(uint2*)&As[0][ar][ac] = make_uint2(pack_bf16x2(pa0.x, pa0.y), pack_bf16x2(pa0.z, pa0.w));
    *(uint4*)&Bs[0][br][bc]      = pb0;
    *(uint4*)&Bs[0][br + 64][bc] = pb1;
    __syncthreads();

    const int NKT = (NN / SPLIT1) / 32;
    for (int kt = 0; kt < NKT; ++kt) {
        const int s = kt & 1;
        if (kt + 1 < NKT) {
            const int ko = ks0 + (kt + 1) * 32;
            pa0 = __ldcs((const float4*)&A[(size_t)(r0 + ar) * NN + ko + ac]);
            pb0 = *(const uint4*)&g_C1t[(size_t)br * NN + ko + bc];
            pb1 = *(const uint4*)&g_C1t[(size_t)(br + 64) * NN + ko + bc];
        }
#pragma unroll
        for (int ks = 0; ks < 32; ks += 16) {
            uint32_t a[4];
            a[0] = *(uint32_t*)&As[s][m0 + g    ][ks + 2 * t    ];
            a[1] = *(uint32_t*)&As[s][m0 + g + 8][ks + 2 * t    ];
            a[2] = *(uint32_t*)&As[s][m0 + g    ][ks + 2 * t + 8];
            a[3] = *(uint32_t*)&As[s][m0 + g + 8][ks + 2 * t + 8];
#pragma unroll
            for (int f = 0; f < 4; ++f) {
                uint32_t b[2];
                b[0] = *(uint32_t*)&Bs[s][n0 + f * 8 + g][ks + 2 * t    ];
                b[1] = *(uint32_t*)&Bs[s][n0 + f * 8 + g][ks + 2 * t + 8];
                mma_bf16(acc[f], a, b);
            }
        }
        if (kt + 1 < NKT) {
            const int d = s ^ 1;
            *(uint2*)&As[d][ar][ac] = make_uint2(pack_bf16x2(pa0.x, pa0.y), pack_bf16x2(pa0.z, pa0.w));
            *(uint4*)&Bs[d][br][bc]      = pb0;
            *(uint4*)&Bs[d][br + 64][bc] = pb1;
            __syncthreads();
        }
    }

    float* P = g_P1 + (size_t)sp * NN * HID;
#pragma unroll
    for (int f = 0; f < 4; ++f) {
        const int col = n0 + f * 8 + 2 * t;
        const int row = r0 + m0 + g;
        *(float2*)&P[(size_t)row * HID + col]       = make_float2(acc[f][0], acc[f][1]);
        *(float2*)&P[(size_t)(row + 8) * HID + col] = make_float2(acc[f][2], acc[f][3]);
    }
}

// ---------------------------------------------------------------------------
// kr1: H = relu(sum P1), then C2t = (H @ W2)^T bf16 (fused).
// grid 256 (32 rows/CTA), block 256.
// ---------------------------------------------------------------------------
__global__ __launch_bounds__(256) void kr1_reduce_w2(const float* __restrict__ W2) {
    __shared__ float Hs[32][128];
    __shared__ float Ws[HID * LAT];
    const int tid = threadIdx.x;
    const int r0  = blockIdx.x * 32;

#pragma unroll
    for (int j = 0; j < 4; ++j)
        ((float4*)Ws)[tid + j * 256] = ((const float4*)W2)[tid + j * 256];

#pragma unroll
    for (int j = 0; j < 4; ++j) {
        int id = tid + j * 256;
        int rr = id >> 5, cc = (id & 31) * 4;
        size_t off = (size_t)(r0 + rr) * HID + cc;
        float4 s = *(const float4*)&g_P1[off];
#pragma unroll
        for (int p = 1; p < SPLIT1; ++p) {
            float4 v = *(const float4*)&g_P1[(size_t)p * NN * HID + off];
            s.x += v.x; s.y += v.y; s.z += v.z; s.w += v.w;
        }
        s.x = fmaxf(s.x, 0.0f); s.y = fmaxf(s.y, 0.0f);
        s.z = fmaxf(s.z, 0.0f); s.w = fmaxf(s.w, 0.0f);
        *(float4*)&Hs[rr][cc] = s;
    }
    __syncthreads();

    const int c = tid & 31, rb = tid >> 5;
    float acc[4];
#pragma unroll
    for (int i = 0; i < 4; ++i) acc[i] = 0.0f;
    for (int k = 0; k < HID; ++k) {
        float w = Ws[k * LAT + c];
#pragma unroll
        for (int i = 0; i < 4; ++i) acc[i] += Hs[rb + i * 8][k] * w;
    }
#pragma unroll
    for (int i = 0; i < 4; ++i)
        g_C2t[(size_t)c * NN + r0 + rb + i * 8] = __float2bfloat16(acc[i]);
}

// ---------------------------------------------------------------------------
// k3: split-K partial of A @ C2. BM=32, BN=32, BK=64.
// grid (256, SPLIT2) = 4096 CTAs, 128 thr, double-buffered.
// ---------------------------------------------------------------------------
__global__ __launch_bounds__(128) void k3_gemm2(const float* __restrict__ A) {
    __shared__ __nv_bfloat16 As[2][32][72];
    __shared__ __nv_bfloat16 Bs[2][32][72];

    const int tid  = threadIdx.x;
    const int warp = tid >> 5, lane = tid & 31;
    const int g = lane >> 2, t = lane & 3;
    const int mw = warp & 1, nw = warp >> 1;
    const int m0 = mw * 16, n0 = nw * 16;
    const int r0  = blockIdx.x * 32;
    const int sp  = blockIdx.y;
    const int ks0 = sp * (NN / SPLIT2);

    const int a0r = tid >> 4, a0c = (tid & 15) * 4;
    const int b0r = tid >> 3, b0c = (tid & 7) * 8;

    float acc[2][4];
#pragma unroll
    for (int f = 0; f < 2; ++f)
#pragma unroll
        for (int j = 0; j < 4; ++j) acc[f][j] = 0.0f;

    float4 pa[4];
    uint4  pb[2];
#pragma unroll
    for (int j = 0; j < 4; ++j)
        pa[j] = __ldcs((const float4*)&A[(size_t)(r0 + a0r + j * 8) * NN + ks0 + a0c]);
#pragma unroll
    for (int j = 0; j < 2; ++j)
        pb[j] = *(const uint4*)&g_C2t[(size_t)(b0r + j * 16) * NN + ks0 + b0c];

#pragma unroll
    for (int j = 0; j < 4; ++j)
        *(uint2*)&As[0][a0r + j * 8][a0c] =
            make_uint2(pack_bf16x2(pa[j].x, pa[j].y), pack_bf16x2(pa[j].z, pa[j].w));
#pragma unroll
    for (int j = 0; j < 2; ++j)
        *(uint4*)&Bs[0][b0r + j * 16][b0c] = pb[j];
    __syncthreads();

    const int NKT = (NN / SPLIT2) / 64;
    for (int kt = 0; kt < NKT; ++kt) {
        const int s = kt & 1;
        if (kt + 1 < NKT) {
            const int ko = ks0 + (kt + 1) * 64;
#pragma unroll
            for (int j = 0; j < 4; ++j)
                pa[j] = __ldcs((const float4*)&A[(size_t)(r0 + a0r + j * 8) * NN + ko + a0c]);
#pragma unroll
            for (int j = 0; j < 2; ++j)
                pb[j] = *(const uint4*)&g_C2t[(size_t)(b0r + j * 16) * NN + ko + b0c];
        }
#pragma unroll
        for (int ks = 0; ks < 64; ks += 16) {
            uint32_t a[4];
            a[0] = *(uint32_t*)&As[s][m0 + g    ][ks + 2 * t    ];
            a[1] = *(uint32_t*)&As[s][m0 + g + 8][ks + 2 * t    ];
            a[2] = *(uint32_t*)&As[s][m0 + g    ][ks + 2 * t + 8];
            a[3] = *(uint32_t*)&As[s][m0 + g + 8][ks + 2 * t + 8];
#pragma unroll
            for (int f = 0; f < 2; ++f) {
                uint32_t b[2];
                b[0] = *(uint32_t*)&Bs[s][n0 + f * 8 + g][ks + 2 * t    ];
                b[1] = *(uint32_t*)&Bs[s][n0 + f * 8 + g][ks + 2 * t + 8];
                mma_bf16(acc[f], a, b);
            }
        }
        if (kt + 1 < NKT) {
            const int d = s ^ 1;
#pragma unroll
            for (int j = 0; j < 4; ++j)
                *(uint2*)&As[d][a0r + j * 8][a0c] =
                    make_uint2(pack_bf16x2(pa[j].x, pa[j].y), pack_bf16x2(pa[j].z, pa[j].w));
#pragma unroll
            for (int j = 0; j < 2; ++j)
                *(uint4*)&Bs[d][b0r + j * 16][b0c] = pb[j];
            __syncthreads();
        }
    }

    float* P = g_P2 + (size_t)sp * NN * LAT;
#pragma unroll
    for (int f = 0; f < 2; ++f) {
        const int col = n0 + f * 8 + 2 * t;
        const int row = r0 + m0 + g;
        *(float2*)&P[(size_t)row * LAT + col]       = make_float2(acc[f][0], acc[f][1]);
        *(float2*)&P[(size_t)(row + 8) * LAT + col] = make_float2(acc[f][2], acc[f][3]);
    }
}

// ---------------------------------------------------------------------------
// kr2: Z = sum P2 -> bf16. grid 64, block 256, 4 float4/thr.
// ---------------------------------------------------------------------------
__global__ __launch_bounds__(256) void kr2_reduce(void) {
    const int tid = blockIdx.x * 256 + threadIdx.x;   // 16384 threads
#pragma unroll
    for (int j = 0; j < 4; ++j) {
        size_t pos = (size_t)(tid + j * 16384);       // float4 index, 65536 total
        float4 s = ((const float4*)g_P2)[pos];
#pragma unroll
        for (int p = 1; p < SPLIT2; ++p) {
            float4 v = ((const float4*)g_P2)[(size_t)p * (NN * LAT / 4) + pos];
            s.x += v.x; s.y += v.y; s.z += v.z; s.w += v.w;
        }
        uint2 packed = make_uint2(pack_bf16x2(s.x, s.y), pack_bf16x2(s.z, s.w));
        *(uint2*)&g_Z[pos * 4] = packed;
    }
}

// ---------------------------------------------------------------------------
// k4: out = sigmoid(Z @ Z^T). 128x128 tile/block, grid 64x64, K=32.
// Two n-passes (4 frags each) halve acc registers -> higher occupancy.
// ---------------------------------------------------------------------------
__global__ __launch_bounds__(256) void k4_decoder(float* __restrict__ out) {
    __shared__ __nv_bfloat16 Zi[128][40];
    __shared__ __nv_bfloat16 Zj[128][40];
    const int tid  = threadIdx.x;
    const int warp = tid >> 5, lane = tid & 31;
    const int g = lane >> 2, t = lane & 3;
    const int m0 = (warp & 3) * 32, n0 = (warp >> 2) * 64;
    const size_t i0 = (size_t)blockIdx.y * 128;
    const size_t j0 = (size_t)blockIdx.x * 128;

#pragma unroll
    for (int j = 0; j < 2; ++j) {
        int id = tid + j * 256;
        int rr = id >> 2, kk = (id & 3) * 8;
        *(uint4*)&Zi[rr][kk] = *(const uint4*)&g_Z[(i0 + rr) * LAT + kk];
        *(uint4*)&Zj[rr][kk] = *(const uint4*)&g_Z[(j0 + rr) * LAT + kk];
    }
    __syncthreads();

#pragma unroll
    for (int half = 0; half < 2; ++half) {
        float acc[2][4][4];
#pragma unroll
        for (int mt = 0; mt < 2; ++mt)
#pragma unroll
            for (int f = 0; f < 4; ++f)
#pragma unroll
                for (int j = 0; j < 4; ++j) acc[mt][f][j] = 0.0f;

#pragma unroll
        for (int ks = 0; ks < 32; ks += 16) {
            uint32_t a[2][4];
#pragma unroll
            for (int mt = 0; mt < 2; ++mt) {
                int mr = m0 + mt * 16;
                a[mt][0] = *(uint32_t*)&Zi[mr + g    ][ks + 2 * t    ];
                a[mt][1] = *(uint32_t*)&Zi[mr + g + 8][ks + 2 * t    ];
                a[mt][2] = *(uint32_t*)&Zi[mr + g    ][ks + 2 * t + 8];
                a[mt][3] = *(uint32_t*)&Zi[mr + g + 8][ks + 2 * t + 8];
            }
#pragma unroll
            for (int f = 0; f < 4; ++f) {
                const int fi = half * 4 + f;
                uint32_t b[2];
                b[0] = *(uint32_t*)&Zj[n0 + fi * 8 + g][ks + 2 * t    ];
                b[1] = *(uint32_t*)&Zj[n0 + fi * 8 + g][ks + 2 * t + 8];
#pragma unroll
                for (int mt = 0; mt < 2; ++mt) mma_bf16(acc[mt][f], a[mt], b);
            }
        }

#pragma unroll
        for (int mt = 0; mt < 2; ++mt) {
#pragma unroll
            for (int f = 0; f < 4; ++f) {
                const int fi = half * 4 + f;
                size_t row = i0 + m0 + mt * 16 + g;
                size_t col = j0 + n0 + fi * 8 + 2 * t;
                float2 v0 = make_float2(sigmoid_f(acc[mt][f][0]), sigmoid_f(acc[mt][f][1]));
                float2 v1 = make_float2(sigmoid_f(acc[mt][f][2]), sigmoid_f(acc[mt][f][3]));
                __stcs((float2*)&out[row * NN + col], v0);
                __stcs((float2*)&out[(row + 8) * NN + col], v1);
            }
        }
    }
}

// ---------------------------------------------------------------------------
extern "C" void kernel_launch(void* const* d_in, const int* in_sizes, int n_in,
                              void* d_out, int out_size) {
    const float* X  = (const float*)d_in[0];
    const float* A  = (const float*)d_in[1];
    const float* W1 = (const float*)d_in[2];
    const float* W2 = (const float*)d_in[3];
    float* out = (float*)d_out;
    (void)in_sizes; (void)n_in; (void)out_size;

    k0_xw1  <<<NN / 32, 256>>>(X, W1);
    k1_gemm1<<<dim3(NN / 32, SPLIT1), 256>>>(A);
    kr1_reduce_w2<<<NN / 32, 256>>>(W2);
    k3_gemm2<<<dim3(NN / 32, SPLIT2), 128>>>(A);
    kr2_reduce<<<64, 256>>>();
    dim3 grid(NN / 128, NN / 128);
    k4_decoder<<<grid, 256>>>(out);
}

// round 8
// speedup vs baseline: 1.2993x; 1.2993x over previous
#include <cuda_runtime.h>
#include <cuda_bf16.h>
#include <stdint.h>

// GAE forward: A_hat = sigmoid(Z Z^T), Z = A @ (relu(A @ (X W1)) @ W2)
// N=8192, F_IN=256, HID=128, LAT=32.
// Round 8: revert to the measured round-6 composition (278us); keep the
// measured k3 SPLIT2=16 win; single new change = SPLIT1 4->8 on round-6 k1.

constexpr int NN  = 8192;
constexpr int FIN = 256;
constexpr int HID = 128;
constexpr int LAT = 32;

constexpr int SPLIT1 = 8;    // k1: grid (128, 8)  = 1024 CTAs (7 CTAs/SM by smem)
constexpr int SPLIT2 = 16;   // k3: grid (256, 16) = 4096 CTAs (measured win)

__device__ __nv_bfloat16 g_C1t[HID * NN];          // (X W1)^T  [128][8192] bf16
__device__ __nv_bfloat16 g_C2t[LAT * NN];          // (H W2)^T  [32][8192]  bf16
__device__ __nv_bfloat16 g_Z  [NN * LAT];          // Z         [8192][32]  bf16
__device__ float g_P1[SPLIT1 * NN * HID];          // k1 partials (32 MB)
__device__ float g_P2[SPLIT2 * NN * LAT];          // k3 partials (16 MB)

__device__ __forceinline__ void mma_bf16(float c[4], const uint32_t a[4], const uint32_t b[2]) {
    asm volatile(
        "mma.sync.aligned.m16n8k16.row.col.f32.bf16.bf16.f32 "
        "{%0,%1,%2,%3}, {%4,%5,%6,%7}, {%8,%9}, {%0,%1,%2,%3};\n"
        : "+f"(c[0]), "+f"(c[1]), "+f"(c[2]), "+f"(c[3])
        : "r"(a[0]), "r"(a[1]), "r"(a[2]), "r"(a[3]), "r"(b[0]), "r"(b[1]));
}

__device__ __forceinline__ uint32_t pack_bf16x2(float x, float y) {
    __nv_bfloat162 v = __float22bfloat162_rn(make_float2(x, y));
    return *reinterpret_cast<uint32_t*>(&v);
}

__device__ __forceinline__ float sigmoid_f(float x) {
    float ax = fabsf(x);
    if (ax < 1.0f) {
        float x2 = x * x;   // |err| < 2.2e-5 on |x|<1; real |x| ~ 1e-8 here
        return 0.5f + x * (0.25f + x2 * (-(1.0f / 48.0f) + x2 * (1.0f / 480.0f)));
    }
    return 1.0f / (1.0f + __expf(-x));
}

// ---------------------------------------------------------------------------
// k0: C1t = (X @ W1)^T as bf16.  SIMT fp32 (round-6 version). grid 128.
// ---------------------------------------------------------------------------
__global__ __launch_bounds__(256) void k0_xw1(const float* __restrict__ X,
                                              const float* __restrict__ W1) {
    __shared__ float Xs[64][32];
    __shared__ float Ws[32][128];
    const int tid = threadIdx.x;
    const int r0  = blockIdx.x * 64;
    const int ty  = tid >> 5, tx = tid & 31;

    float acc[8][4];
#pragma unroll
    for (int i = 0; i < 8; ++i)
#pragma unroll
        for (int j = 0; j < 4; ++j) acc[i][j] = 0.0f;

    for (int kt = 0; kt < FIN; kt += 32) {
#pragma unroll
        for (int j = 0; j < 2; ++j) {
            int id = tid + j * 256;
            int rr = id >> 3, cc = (id & 7) * 4;
            *(float4*)&Xs[rr][cc] = *(const float4*)&X[(size_t)(r0 + rr) * FIN + kt + cc];
        }
#pragma unroll
        for (int j = 0; j < 4; ++j) {
            int id = tid + j * 256;
            int rr = id >> 5, cc = (id & 31) * 4;
            *(float4*)&Ws[rr][cc] = *(const float4*)&W1[(size_t)(kt + rr) * HID + cc];
        }
        __syncthreads();
#pragma unroll
        for (int k = 0; k < 32; ++k) {
            float4 b = *(float4*)&Ws[k][tx * 4];
#pragma unroll
            for (int i = 0; i < 8; ++i) {
                float a = Xs[ty * 8 + i][k];
                acc[i][0] += a * b.x;
                acc[i][1] += a * b.y;
                acc[i][2] += a * b.z;
                acc[i][3] += a * b.w;
            }
        }
        __syncthreads();
    }
#pragma unroll
    for (int i = 0; i < 8; ++i)
#pragma unroll
        for (int j = 0; j < 4; ++j)
            g_C1t[(size_t)(tx * 4 + j) * NN + r0 + ty * 8 + i] = __float2bfloat16(acc[i][j]);
}

// ---------------------------------------------------------------------------
// k1: split-K partial of A @ C1. BM=64, BN=128, BK=32 (round-6 shape).
// grid (128, SPLIT1) = 1024 CTAs, 256 thr, double-buffered smem.
// Warps 2m x 4n (32x32 warp tile). Writes fp32 partials.
// ---------------------------------------------------------------------------
__global__ __launch_bounds__(256) void k1_gemm1(const float* __restrict__ A) {
    __shared__ __nv_bfloat16 As[2][64][40];
    __shared__ __nv_bfloat16 Bs[2][128][40];

    const int tid  = threadIdx.x;
    const int warp = tid >> 5, lane = tid & 31;
    const int g = lane >> 2, t = lane & 3;
    const int mw = warp & 1, nw = warp >> 1;
    const int m0 = mw * 32, n0 = nw * 32;
    const int r0  = blockIdx.x * 64;
    const int sp  = blockIdx.y;
    const int ks0 = sp * (NN / SPLIT1);

    const int ar = tid >> 3, ac = (tid & 7) * 4;
    const int br = tid >> 2, bc = (tid & 3) * 8;

    float acc[2][4][4];
#pragma unroll
    for (int mi = 0; mi < 2; ++mi)
#pragma unroll
        for (int f = 0; f < 4; ++f)
#pragma unroll
            for (int j = 0; j < 4; ++j) acc[mi][f][j] = 0.0f;

    float4 pa0, pa1;
    uint4  pb0, pb1;
    pa0 = __ldcs((const float4*)&A[(size_t)(r0 + ar) * NN + ks0 + ac]);
    pa1 = __ldcs((const float4*)&A[(size_t)(r0 + ar + 32) * NN + ks0 + ac]);
    pb0 = *(const uint4*)&g_C1t[(size_t)br * NN + ks0 + bc];
    pb1 = *(const uint4*)&g_C1t[(size_t)(br + 64) * NN + ks0 + bc];

    *(uint2*)&As[0][ar][ac]      = make_uint2(pack_bf16x2(pa0.x, pa0.y), pack_bf16x2(pa0.z, pa0.w));
    *(uint2*)&As[0][ar + 32][ac] = make_uint2(pack_bf16x2(pa1.x, pa1.y), pack_bf16x2(pa1.z, pa1.w));
    *(uint4*)&Bs[0][br][bc]      = pb0;
    *(uint4*)&Bs[0][br + 64][bc] = pb1;
    __syncthreads();

    const int NKT = (NN / SPLIT1) / 32;
    for (int kt = 0; kt < NKT; ++kt) {
        const int s = kt & 1;
        if (kt + 1 < NKT) {
            const int ko = ks0 + (kt + 1) * 32;
            pa0 = __ldcs((const float4*)&A[(size_t)(r0 + ar) * NN + ko + ac]);
            pa1 = __ldcs((const float4*)&A[(size_t)(r0 + ar + 32) * NN + ko + ac]);
            pb0 = *(const uint4*)&g_C1t[(size_t)br * NN + ko + bc];
            pb1 = *(const uint4*)&g_C1t[(size_t)(br + 64) * NN + ko + bc];
        }
#pragma unroll
        for (int ks = 0; ks < 32; ks += 16) {
            uint32_t a[2][4];
#pragma unroll
            for (int mi = 0; mi < 2; ++mi) {
                const int mr = m0 + mi * 16;
                a[mi][0] = *(uint32_t*)&As[s][mr + g    ][ks + 2 * t    ];
                a[mi][1] = *(uint32_t*)&As[s][mr + g + 8][ks + 2 * t    ];
                a[mi][2] = *(uint32_t*)&As[s][mr + g    ][ks + 2 * t + 8];
                a[mi][3] = *(uint32_t*)&As[s][mr + g + 8][ks + 2 * t + 8];
            }
#pragma unroll
            for (int f = 0; f < 4; ++f) {
                uint32_t b[2];
                b[0] = *(uint32_t*)&Bs[s][n0 + f * 8 + g][ks + 2 * t    ];
                b[1] = *(uint32_t*)&Bs[s][n0 + f * 8 + g][ks + 2 * t + 8];
#pragma unroll
                for (int mi = 0; mi < 2; ++mi) mma_bf16(acc[mi][f], a[mi], b);
            }
        }
        if (kt + 1 < NKT) {
            const int d = s ^ 1;
            *(uint2*)&As[d][ar][ac]      = make_uint2(pack_bf16x2(pa0.x, pa0.y), pack_bf16x2(pa0.z, pa0.w));
            *(uint2*)&As[d][ar + 32][ac] = make_uint2(pack_bf16x2(pa1.x, pa1.y), pack_bf16x2(pa1.z, pa1.w));
            *(uint4*)&Bs[d][br][bc]      = pb0;
            *(uint4*)&Bs[d][br + 64][bc] = pb1;
            __syncthreads();
        }
    }

    float* P = g_P1 + (size_t)sp * NN * HID;
#pragma unroll
    for (int mi = 0; mi < 2; ++mi) {
#pragma unroll
        for (int f = 0; f < 4; ++f) {
            const int col = n0 + f * 8 + 2 * t;
            const int row = r0 + m0 + mi * 16 + g;
            *(float2*)&P[(size_t)row * HID + col] =
                make_float2(acc[mi][f][0], acc[mi][f][1]);
            *(float2*)&P[(size_t)(row + 8) * HID + col] =
                make_float2(acc[mi][f][2], acc[mi][f][3]);
        }
    }
}

// ---------------------------------------------------------------------------
// kr1: H = relu(sum P1), then C2t = (H @ W2)^T bf16 (fused).
// grid 256 (32 rows/CTA), block 256.
// ---------------------------------------------------------------------------
__global__ __launch_bounds__(256) void kr1_reduce_w2(const float* __restrict__ W2) {
    __shared__ float Hs[32][128];
    __shared__ float Ws[HID * LAT];
    const int tid = threadIdx.x;
    const int r0  = blockIdx.x * 32;

#pragma unroll
    for (int j = 0; j < 4; ++j)
        ((float4*)Ws)[tid + j * 256] = ((const float4*)W2)[tid + j * 256];

#pragma unroll
    for (int j = 0; j < 4; ++j) {
        int id = tid + j * 256;
        int rr = id >> 5, cc = (id & 31) * 4;
        size_t off = (size_t)(r0 + rr) * HID + cc;
        float4 s = *(const float4*)&g_P1[off];
#pragma unroll
        for (int p = 1; p < SPLIT1; ++p) {
            float4 v = *(const float4*)&g_P1[(size_t)p * NN * HID + off];
            s.x += v.x; s.y += v.y; s.z += v.z; s.w += v.w;
        }
        s.x = fmaxf(s.x, 0.0f); s.y = fmaxf(s.y, 0.0f);
        s.z = fmaxf(s.z, 0.0f); s.w = fmaxf(s.w, 0.0f);
        *(float4*)&Hs[rr][cc] = s;
    }
    __syncthreads();

    const int c = tid & 31, rb = tid >> 5;
    float acc[4];
#pragma unroll
    for (int i = 0; i < 4; ++i) acc[i] = 0.0f;
    for (int k = 0; k < HID; ++k) {
        float w = Ws[k * LAT + c];
#pragma unroll
        for (int i = 0; i < 4; ++i) acc[i] += Hs[rb + i * 8][k] * w;
    }
#pragma unroll
    for (int i = 0; i < 4; ++i)
        g_C2t[(size_t)c * NN + r0 + rb + i * 8] = __float2bfloat16(acc[i]);
}

// ---------------------------------------------------------------------------
// k3: split-K partial of A @ C2. BM=32, BN=32, BK=64.
// grid (256, SPLIT2) = 4096 CTAs, 128 thr, double-buffered. (measured 51us)
// ---------------------------------------------------------------------------
__global__ __launch_bounds__(128) void k3_gemm2(const float* __restrict__ A) {
    __shared__ __nv_bfloat16 As[2][32][72];
    __shared__ __nv_bfloat16 Bs[2][32][72];

    const int tid  = threadIdx.x;
    const int warp = tid >> 5, lane = tid & 31;
    const int g = lane >> 2, t = lane & 3;
    const int mw = warp & 1, nw = warp >> 1;
    const int m0 = mw * 16, n0 = nw * 16;
    const int r0  = blockIdx.x * 32;
    const int sp  = blockIdx.y;
    const int ks0 = sp * (NN / SPLIT2);

    const int a0r = tid >> 4, a0c = (tid & 15) * 4;
    const int b0r = tid >> 3, b0c = (tid & 7) * 8;

    float acc[2][4];
#pragma unroll
    for (int f = 0; f < 2; ++f)
#pragma unroll
        for (int j = 0; j < 4; ++j) acc[f][j] = 0.0f;

    float4 pa[4];
    uint4  pb[2];
#pragma unroll
    for (int j = 0; j < 4; ++j)
        pa[j] = __ldcs((const float4*)&A[(size_t)(r0 + a0r + j * 8) * NN + ks0 + a0c]);
#pragma unroll
    for (int j = 0; j < 2; ++j)
        pb[j] = *(const uint4*)&g_C2t[(size_t)(b0r + j * 16) * NN + ks0 + b0c];

#pragma unroll
    for (int j = 0; j < 4; ++j)
        *(uint2*)&As[0][a0r + j * 8][a0c] =
            make_uint2(pack_bf16x2(pa[j].x, pa[j].y), pack_bf16x2(pa[j].z, pa[j].w));
#pragma unroll
    for (int j = 0; j < 2; ++j)
        *(uint4*)&Bs[0][b0r + j * 16][b0c] = pb[j];
    __syncthreads();

    const int NKT = (NN / SPLIT2) / 64;
    for (int kt = 0; kt < NKT; ++kt) {
        const int s = kt & 1;
        if (kt + 1 < NKT) {
            const int ko = ks0 + (kt + 1) * 64;
#pragma unroll
            for (int j = 0; j < 4; ++j)
                pa[j] = __ldcs((const float4*)&A[(size_t)(r0 + a0r + j * 8) * NN + ko + a0c]);
#pragma unroll
            for (int j = 0; j < 2; ++j)
                pb[j] = *(const uint4*)&g_C2t[(size_t)(b0r + j * 16) * NN + ko + b0c];
        }
#pragma unroll
        for (int ks = 0; ks < 64; ks += 16) {
            uint32_t a[4];
            a[0] = *(uint32_t*)&As[s][m0 + g    ][ks + 2 * t    ];
            a[1] = *(uint32_t*)&As[s][m0 + g + 8][ks + 2 * t    ];
            a[2] = *(uint32_t*)&As[s][m0 + g    ][ks + 2 * t + 8];
            a[3] = *(uint32_t*)&As[s][m0 + g + 8][ks + 2 * t + 8];
#pragma unroll
            for (int f = 0; f < 2; ++f) {
                uint32_t b[2];
                b[0] = *(uint32_t*)&Bs[s][n0 + f * 8 + g][ks + 2 * t    ];
                b[1] = *(uint32_t*)&Bs[s][n0 + f * 8 + g][ks + 2 * t + 8];
                mma_bf16(acc[f], a, b);
            }
        }
        if (kt + 1 < NKT) {
            const int d = s ^ 1;
#pragma unroll
            for (int j = 0; j < 4; ++j)
                *(uint2*)&As[d][a0r + j * 8][a0c] =
                    make_uint2(pack_bf16x2(pa[j].x, pa[j].y), pack_bf16x2(pa[j].z, pa[j].w));
#pragma unroll
            for (int j = 0; j < 2; ++j)
                *(uint4*)&Bs[d][b0r + j * 16][b0c] = pb[j];
            __syncthreads();
        }
    }

    float* P = g_P2 + (size_t)sp * NN * LAT;
#pragma unroll
    for (int f = 0; f < 2; ++f) {
        const int col = n0 + f * 8 + 2 * t;
        const int row = r0 + m0 + g;
        *(float2*)&P[(size_t)row * LAT + col]       = make_float2(acc[f][0], acc[f][1]);
        *(float2*)&P[(size_t)(row + 8) * LAT + col] = make_float2(acc[f][2], acc[f][3]);
    }
}

// ---------------------------------------------------------------------------
// kr2: Z = sum P2 -> bf16. grid 64, block 256, 4 float4/thr.
// ---------------------------------------------------------------------------
__global__ __launch_bounds__(256) void kr2_reduce(void) {
    const int tid = blockIdx.x * 256 + threadIdx.x;   // 16384 threads
#pragma unroll
    for (int j = 0; j < 4; ++j) {
        size_t pos = (size_t)(tid + j * 16384);       // float4 index, 65536 total
        float4 s = ((const float4*)g_P2)[pos];
#pragma unroll
        for (int p = 1; p < SPLIT2; ++p) {
            float4 v = ((const float4*)g_P2)[(size_t)p * (NN * LAT / 4) + pos];
            s.x += v.x; s.y += v.y; s.z += v.z; s.w += v.w;
        }
        uint2 packed = make_uint2(pack_bf16x2(s.x, s.y), pack_bf16x2(s.z, s.w));
        *(uint2*)&g_Z[pos * 4] = packed;
    }
}

// ---------------------------------------------------------------------------
// k4: out = sigmoid(Z @ Z^T). 128x128 tile/block, grid 64x64, K=32.
// (round-6 single-pass version; __stcs streaming stores)
// ---------------------------------------------------------------------------
__global__ __launch_bounds__(256) void k4_decoder(float* __restrict__ out) {
    __shared__ __nv_bfloat16 Zi[128][40];
    __shared__ __nv_bfloat16 Zj[128][40];
    const int tid  = threadIdx.x;
    const int warp = tid >> 5, lane = tid & 31;
    const int g = lane >> 2, t = lane & 3;
    const int m0 = (warp & 3) * 32, n0 = (warp >> 2) * 64;
    const size_t i0 = (size_t)blockIdx.y * 128;
    const size_t j0 = (size_t)blockIdx.x * 128;

#pragma unroll
    for (int j = 0; j < 2; ++j) {
        int id = tid + j * 256;
        int rr = id >> 2, kk = (id & 3) * 8;
        *(uint4*)&Zi[rr][kk] = *(const uint4*)&g_Z[(i0 + rr) * LAT + kk];
        *(uint4*)&Zj[rr][kk] = *(const uint4*)&g_Z[(j0 + rr) * LAT + kk];
    }
    __syncthreads();

    float acc[2][8][4];
#pragma unroll
    for (int mt = 0; mt < 2; ++mt)
#pragma unroll
        for (int f = 0; f < 8; ++f)
#pragma unroll
            for (int j = 0; j < 4; ++j) acc[mt][f][j] = 0.0f;

#pragma unroll
    for (int ks = 0; ks < 32; ks += 16) {
        uint32_t a[2][4];
#pragma unroll
        for (int mt = 0; mt < 2; ++mt) {
            int mr = m0 + mt * 16;
            a[mt][0] = *(uint32_t*)&Zi[mr + g    ][ks + 2 * t    ];
            a[mt][1] = *(uint32_t*)&Zi[mr + g + 8][ks + 2 * t    ];
            a[mt][2] = *(uint32_t*)&Zi[mr + g    ][ks + 2 * t + 8];
            a[mt][3] = *(uint32_t*)&Zi[mr + g + 8][ks + 2 * t + 8];
        }
#pragma unroll
        for (int f = 0; f < 8; ++f) {
            uint32_t b[2];
            b[0] = *(uint32_t*)&Zj[n0 + f * 8 + g][ks + 2 * t    ];
            b[1] = *(uint32_t*)&Zj[n0 + f * 8 + g][ks + 2 * t + 8];
#pragma unroll
            for (int mt = 0; mt < 2; ++mt) mma_bf16(acc[mt][f], a[mt], b);
        }
    }

#pragma unroll
    for (int mt = 0; mt < 2; ++mt) {
#pragma unroll
        for (int f = 0; f < 8; ++f) {
            size_t row = i0 + m0 + mt * 16 + g;
            size_t col = j0 + n0 + f * 8 + 2 * t;
            float2 v0 = make_float2(sigmoid_f(acc[mt][f][0]), sigmoid_f(acc[mt][f][1]));
            float2 v1 = make_float2(sigmoid_f(acc[mt][f][2]), sigmoid_f(acc[mt][f][3]));
            __stcs((float2*)&out[row * NN + col], v0);
            __stcs((float2*)&out[(row + 8) * NN + col], v1);
        }
    }
}

// ---------------------------------------------------------------------------
extern "C" void kernel_launch(void* const* d_in, const int* in_sizes, int n_in,
                              void* d_out, int out_size) {
    const float* X  = (const float*)d_in[0];
    const float* A  = (const float*)d_in[1];
    const float* W1 = (const float*)d_in[2];
    const float* W2 = (const float*)d_in[3];
    float* out = (float*)d_out;
    (void)in_sizes; (void)n_in; (void)out_size;

    k0_xw1  <<<NN / 64, 256>>>(X, W1);
    k1_gemm1<<<dim3(NN / 64, SPLIT1), 256>>>(A);
    kr1_reduce_w2<<<NN / 32, 256>>>(W2);
    k3_gemm2<<<dim3(NN / 32, SPLIT2), 128>>>(A);
    kr2_reduce<<<64, 256>>>();
    dim3 grid(NN / 128, NN / 128);
    k4_decoder<<<grid, 256>>>(out);
}